// round 9
// baseline (speedup 1.0000x reference)
#include <cuda_runtime.h>
#include <cuda_bf16.h>

// B=512, T=1024, IN=1, H=64
#define TLEN 1024
#define HDIM 64
#define GB   2              // batches per block (weights shared across both)
#define NTHR 256            // 64 units x 2 k-halves x 2 gate-pairs
#define NBLK 256            // 512 / GB -> 2 co-resident blocks per SM

typedef unsigned long long u64;

__device__ __forceinline__ u64 fma2(u64 a, u64 b, u64 c) {
    u64 d;
    asm("fma.rn.f32x2 %0, %1, %2, %3;" : "=l"(d) : "l"(a), "l"(b), "l"(c));
    return d;
}
__device__ __forceinline__ u64 pack2(float lo, float hi) {
    u64 r;
    asm("mov.b64 %0, {%1, %2};" : "=l"(r) : "f"(lo), "f"(hi));
    return r;
}
__device__ __forceinline__ float lo_add_hi(u64 v) {
    float lo, hi;
    asm("mov.b64 {%0, %1}, %2;" : "=f"(lo), "=f"(hi) : "l"(v));
    return lo + hi;
}
__device__ __forceinline__ float ex2f(float x) {
    float r; asm("ex2.approx.f32 %0, %1;" : "=f"(r) : "f"(x)); return r;
}
__device__ __forceinline__ float rcpf(float x) {
    float r; asm("rcp.approx.f32 %0, %1;" : "=f"(r) : "f"(x)); return r;
}
// Gate rows are PRE-SCALED by -log2(e) (sigmoid rows) or -2*log2(e) (tanh row):
//   sigmoid(a) = 1/(1+ex2(z));   tanh(a) = 2/(1+ex2(z)) - 1
#define NLOG2E  1.44269504f
#define N2LOG2E 2.88539008f

__global__ void __launch_bounds__(NTHR, 2) qlstm_kernel(
    const float* __restrict__ x,      // [512, 1024, 1]
    const float* __restrict__ W_ih,   // [256, 1]
    const float* __restrict__ W_hh,   // [256, 64]
    const float* __restrict__ b_ih,   // [256]
    const float* __restrict__ b_hh,   // [256]
    const float* __restrict__ W_lin,  // [1, 64]
    const float* __restrict__ b_lin,  // [1]
    float* __restrict__ out)          // [512]
{
    __shared__ __align__(16) float xs[GB][TLEN];       // 8 KB
    __shared__ __align__(16) float hsm[2][GB][HDIM];   // 1 KB, double-buffered

    const int tid = threadIdx.x;
    const int p   = tid & 1;           // 0 -> gates {i,f}; 1 -> gates {g,o}
    const int s   = (tid >> 1) & 1;    // k-half: cols [32s, 32s+32)
    const int m   = tid >> 2;          // hidden unit 0..63
    const int bb  = blockIdx.x * GB;

    // ---- stage x (coalesced, one-time) ----
    for (int i = tid; i < GB * TLEN; i += NTHR)
        xs[i >> 10][i & (TLEN - 1)] = x[(bb + (i >> 10)) * TLEN + (i & (TLEN - 1))];

    // ---- 2 half-K W_hh rows -> regs, prescaled (64 regs) ----
    const int   r0   = p ? 128 + m : m;        // g-row  : i-row
    const int   r1   = p ? 192 + m : 64 + m;   // o-row  : f-row
    const float scl0 = p ? -N2LOG2E : -NLOG2E; // tanh row gets 2x scale
    const float scl1 = -NLOG2E;

    u64 w0[16], w1[16];
    {
        const float4* a = reinterpret_cast<const float4*>(W_hh + r0 * HDIM + 32 * s);
        const float4* b = reinterpret_cast<const float4*>(W_hh + r1 * HDIM + 32 * s);
        #pragma unroll
        for (int k = 0; k < 8; k++) {
            float4 v = a[k];
            w0[2 * k]     = pack2(scl0 * v.x, scl0 * v.y);
            w0[2 * k + 1] = pack2(scl0 * v.z, scl0 * v.w);
            float4 u = b[k];
            w1[2 * k]     = pack2(scl1 * u.x, scl1 * u.y);
            w1[2 * k + 1] = pack2(scl1 * u.z, scl1 * u.w);
        }
    }
    // bias + x folded into the s==0 accumulator only (avoid double count)
    const float fold = (s == 0) ? 1.0f : 0.0f;
    const float wih0 = fold * scl0 * W_ih[r0];
    const float bia0 = fold * scl0 * (b_ih[r0] + b_hh[r0]);
    const float wih1 = fold * scl1 * W_ih[r1];
    const float bia1 = fold * scl1 * (b_ih[r1] + b_hh[r1]);

    for (int i = tid; i < 2 * GB * HDIM; i += NTHR)
        reinterpret_cast<float*>(hsm)[i] = 0.0f;

    float c[GB] = {0.0f, 0.0f};   // live in p==0 lanes (p==1 copy is dead)
    __syncthreads();

    const unsigned FULL = 0xffffffffu;

    auto step = [&](int t, const float (*hin)[HDIM], float (*hout)[HDIM]) {
        #pragma unroll
        for (int g = 0; g < GB; g++) {
            // half h (32 floats) as 16 packed pairs; broadcast LDS.128
            const ulonglong2* hp =
                reinterpret_cast<const ulonglong2*>(hin[g] + 32 * s);
            u64 h2[16];
            #pragma unroll
            for (int k = 0; k < 8; k++) {
                ulonglong2 v = hp[k];
                h2[2 * k] = v.x; h2[2 * k + 1] = v.y;
            }
            const float xv = xs[g][t];
            u64 acc0 = pack2(fmaf(xv, wih0, bia0), 0.0f);
            u64 acc1 = pack2(fmaf(xv, wih1, bia1), 0.0f);
            #pragma unroll
            for (int k = 0; k < 16; k++) {
                acc0 = fma2(w0[k], h2[k], acc0);
                acc1 = fma2(w1[k], h2[k], acc1);
            }
            // merge k-halves (lane-xor 2): both halves end with full dot
            float z0 = lo_add_hi(acc0);
            float z1 = lo_add_hi(acc1);
            z0 += __shfl_xor_sync(FULL, z0, 2);
            z1 += __shfl_xor_sync(FULL, z1, 2);

            const float a0 = rcpf(1.0f + ex2f(z0));  // p0: sig(i)  p1: (tanh(g)+1)/2
            const float a1 = rcpf(1.0f + ex2f(z1));  // p0: sig(f)  p1: sig(o)
            const float tga = fmaf(2.0f, a0, -1.0f); // p1: tanh(g)

            // exchange over p (lane-xor 1): p0 receives tanh(g)
            const float trec = __shfl_xor_sync(FULL, p ? tga : a0, 1);
            // p0: c = sig(f)*c + sig(i)*tanh(g)   (p1 lanes: finite garbage)
            c[g] = fmaf(a1, c[g], a0 * trec);
            const float tc = fmaf(2.0f, rcpf(1.0f + ex2f(-N2LOG2E * c[g])), -1.0f);
            // exchange over p: p1 receives tanh(c)
            const float tcx = __shfl_xor_sync(FULL, tc, 1);
            if (p & (1 - s)) hout[g][m] = a1 * tcx;  // h = sig(o)*tanh(c), one writer
        }
    };

    #pragma unroll 1
    for (int t = 0; t < TLEN; t += 2) {
        step(t,     hsm[0], hsm[1]);
        __syncthreads();
        step(t + 1, hsm[1], hsm[0]);
        __syncthreads();
    }
    // t=1023 (odd) wrote hsm[0] -> final h in hsm[0]

    // ---- epilogue: out[b] = h_final . W_lin + b_lin ----
    const int w = tid >> 5, lane = tid & 31;
    if (w < GB) {
        const float* hf = hsm[0][w];
        float v = fmaf(hf[lane], W_lin[lane], hf[lane + 32] * W_lin[lane + 32]);
        #pragma unroll
        for (int d = 16; d >= 1; d >>= 1)
            v += __shfl_xor_sync(FULL, v, d);
        if (lane == 0) out[bb + w] = v + b_lin[0];
    }
}

extern "C" void kernel_launch(void* const* d_in, const int* in_sizes, int n_in,
                              void* d_out, int out_size) {
    const float* x     = (const float*)d_in[0];
    const float* W_ih  = (const float*)d_in[1];
    const float* W_hh  = (const float*)d_in[2];
    const float* b_ih  = (const float*)d_in[3];
    const float* b_hh  = (const float*)d_in[4];
    const float* W_lin = (const float*)d_in[5];
    const float* b_lin = (const float*)d_in[6];
    float* out = (float*)d_out;

    qlstm_kernel<<<NBLK, NTHR>>>(x, W_ih, W_hh, b_ih, b_hh, W_lin, b_lin, out);
}

// round 10
// speedup vs baseline: 1.2391x; 1.2391x over previous
#include <cuda_runtime.h>
#include <cuda_bf16.h>

// B=512, T=1024, IN=1, H=64
#define TLEN 1024
#define HDIM 64
#define GB   2              // batches per block (weights shared across both)
#define NTHR 128            // 64 units x 2 k-halves; each thread owns all 4 gates
#define NBLK 256            // 512 / GB -> 2 co-resident blocks per SM

typedef unsigned long long u64;

__device__ __forceinline__ u64 fma2(u64 a, u64 b, u64 c) {
    u64 d;
    asm("fma.rn.f32x2 %0, %1, %2, %3;" : "=l"(d) : "l"(a), "l"(b), "l"(c));
    return d;
}
__device__ __forceinline__ u64 add2(u64 a, u64 b) {
    u64 d;
    asm("add.rn.f32x2 %0, %1, %2;" : "=l"(d) : "l"(a), "l"(b));
    return d;
}
__device__ __forceinline__ u64 pack2(float lo, float hi) {
    u64 r;
    asm("mov.b64 %0, {%1, %2};" : "=l"(r) : "f"(lo), "f"(hi));
    return r;
}
__device__ __forceinline__ float lo_add_hi(u64 v) {
    float lo, hi;
    asm("mov.b64 {%0, %1}, %2;" : "=f"(lo), "=f"(hi) : "l"(v));
    return lo + hi;
}
__device__ __forceinline__ float ex2f(float x) {
    float r; asm("ex2.approx.f32 %0, %1;" : "=f"(r) : "f"(x)); return r;
}
__device__ __forceinline__ float rcpf(float x) {
    float r; asm("rcp.approx.f32 %0, %1;" : "=f"(r) : "f"(x)); return r;
}
// Gate rows PRE-SCALED by -log2(e) (sigmoid) or -2*log2(e) (tanh):
//   sigmoid(a) = 1/(1+ex2(z));   tanh(a) = 2/(1+ex2(z)) - 1
#define NLOG2E  1.44269504f
#define N2LOG2E 2.88539008f

__global__ void __launch_bounds__(NTHR, 2) qlstm_kernel(
    const float* __restrict__ x,      // [512, 1024, 1]
    const float* __restrict__ W_ih,   // [256, 1]
    const float* __restrict__ W_hh,   // [256, 64]
    const float* __restrict__ b_ih,   // [256]
    const float* __restrict__ b_hh,   // [256]
    const float* __restrict__ W_lin,  // [1, 64]
    const float* __restrict__ b_lin,  // [1]
    float* __restrict__ out)          // [512]
{
    __shared__ __align__(16) float xs[GB][TLEN];       // 8 KB
    __shared__ __align__(16) float hsm[2][GB][HDIM];   // 1 KB, double-buffered

    const int tid = threadIdx.x;
    const int s   = tid & 1;      // k-half: cols [32s, 32s+32)
    const int m   = tid >> 1;     // hidden unit 0..63
    const int bb  = blockIdx.x * GB;

    // ---- stage x (coalesced, one-time) ----
    for (int i = tid; i < GB * TLEN; i += NTHR)
        xs[i >> 10][i & (TLEN - 1)] = x[(bb + (i >> 10)) * TLEN + (i & (TLEN - 1))];

    // ---- 4 half-K W_hh rows (one unit, all gates) -> 64 u64 regs, prescaled ----
    u64 w[4][16];
    float wih[4], bia[4];
    const float fold = (s == 0) ? 1.0f : 0.0f;   // bias/x folded into s==0 half only
    #pragma unroll
    for (int q = 0; q < 4; q++) {
        const float scl = (q == 2) ? -N2LOG2E : -NLOG2E;
        const int row = q * 64 + m;
        const float4* wr = reinterpret_cast<const float4*>(W_hh + row * HDIM + 32 * s);
        #pragma unroll
        for (int k = 0; k < 8; k++) {
            float4 v = wr[k];
            w[q][2 * k]     = pack2(scl * v.x, scl * v.y);
            w[q][2 * k + 1] = pack2(scl * v.z, scl * v.w);
        }
        wih[q] = fold * scl * W_ih[row];
        bia[q] = fold * scl * (b_ih[row] + b_hh[row]);
    }

    for (int i = tid; i < 2 * GB * HDIM; i += NTHR)
        reinterpret_cast<float*>(hsm)[i] = 0.0f;

    float c[GB] = {0.0f, 0.0f};   // both k-half lanes keep identical copies
    __syncthreads();

    const unsigned FULL = 0xffffffffu;

    auto step = [&](int t, const float (*hin)[HDIM], float (*hout)[HDIM]) {
        #pragma unroll
        for (int g = 0; g < GB; g++) {
            // half h (32 floats) as 16 packed pairs; broadcast LDS.128
            const ulonglong2* hp =
                reinterpret_cast<const ulonglong2*>(hin[g] + 32 * s);
            u64 h2[16];
            #pragma unroll
            for (int k = 0; k < 8; k++) {
                ulonglong2 v = hp[k];
                h2[2 * k] = v.x; h2[2 * k + 1] = v.y;
            }
            const float xv = xs[g][t];
            // 4 gates x (2 split accumulators of depth 8) -> 8 indep chains
            u64 aA[4], aB[4];
            #pragma unroll
            for (int q = 0; q < 4; q++) {
                aA[q] = pack2(fmaf(xv, wih[q], bia[q]), 0.0f);
                aB[q] = 0ull;
            }
            #pragma unroll
            for (int k = 0; k < 8; k++) {
                #pragma unroll
                for (int q = 0; q < 4; q++) {
                    aA[q] = fma2(w[q][2 * k],     h2[2 * k],     aA[q]);
                    aB[q] = fma2(w[q][2 * k + 1], h2[2 * k + 1], aB[q]);
                }
            }
            // merge split accs + k-halves (4 parallel shuffles);
            // both lanes end with identical z (a+b == b+a bitwise)
            float z[4];
            #pragma unroll
            for (int q = 0; q < 4; q++) {
                z[q] = lo_add_hi(add2(aA[q], aB[q]));
                z[q] += __shfl_xor_sync(FULL, z[q], 1);
            }
            // thread-local cell update (no cross-lane dependency)
            const float gi = rcpf(1.0f + ex2f(z[0]));
            const float gf = rcpf(1.0f + ex2f(z[1]));
            const float gg = fmaf(2.0f, rcpf(1.0f + ex2f(z[2])), -1.0f);
            const float go = rcpf(1.0f + ex2f(z[3]));
            c[g] = fmaf(gf, c[g], gi * gg);
            const float tc = fmaf(2.0f, rcpf(1.0f + ex2f(-N2LOG2E * c[g])), -1.0f);
            if (s == 0) hout[g][m] = go * tc;
        }
    };

    #pragma unroll 1
    for (int t = 0; t < TLEN; t += 2) {
        step(t,     hsm[0], hsm[1]);
        __syncthreads();
        step(t + 1, hsm[1], hsm[0]);
        __syncthreads();
    }
    // t=1023 (odd) wrote hsm[0] -> final h in hsm[0]

    // ---- epilogue: out[b] = h_final . W_lin + b_lin ----
    const int w8 = tid >> 5, lane = tid & 31;
    if (w8 < GB) {
        const float* hf = hsm[0][w8];
        float v = fmaf(hf[lane], W_lin[lane], hf[lane + 32] * W_lin[lane + 32]);
        #pragma unroll
        for (int d = 16; d >= 1; d >>= 1)
            v += __shfl_xor_sync(FULL, v, d);
        if (lane == 0) out[bb + w8] = v + b_lin[0];
    }
}

extern "C" void kernel_launch(void* const* d_in, const int* in_sizes, int n_in,
                              void* d_out, int out_size) {
    const float* x     = (const float*)d_in[0];
    const float* W_ih  = (const float*)d_in[1];
    const float* W_hh  = (const float*)d_in[2];
    const float* b_ih  = (const float*)d_in[3];
    const float* b_hh  = (const float*)d_in[4];
    const float* W_lin = (const float*)d_in[5];
    const float* b_lin = (const float*)d_in[6];
    float* out = (float*)d_out;

    qlstm_kernel<<<NBLK, NTHR>>>(x, W_ih, W_hh, b_ih, b_hh, W_lin, b_lin, out);
}